// round 12
// baseline (speedup 1.0000x reference)
#include <cuda_runtime.h>
#include <cuda_bf16.h>
#include <math.h>
#include <stdint.h>

// Problem constants (fixed by setup_inputs)
#define T_SEQ 2048
#define EMB   2048
#define NH    32
#define NKV   8
#define HD    64
#define NBLK  32
#define WIN   256
#define KVD   (NKV * HD)   // 512

// fp32 scratch
__device__ float g_q[T_SEQ * NH * HD];     // [t][h][d]
__device__ float g_k[T_SEQ * NKV * HD];    // [t][kv][d]
__device__ float g_v[T_SEQ * NKV * HD];
__device__ int   g_allow[NBLK * NBLK];

// bf16 hi/lo pre-converted operands
__device__ __nv_bfloat16 g_hsh[T_SEQ * EMB], g_hsl[T_SEQ * EMB];
__device__ __nv_bfloat16 g_wqh[EMB * EMB],  g_wql[EMB * EMB];
__device__ __nv_bfloat16 g_wkh[KVD * EMB],  g_wkl[KVD * EMB];
__device__ __nv_bfloat16 g_wvh[KVD * EMB],  g_wvl[KVD * EMB];
__device__ __nv_bfloat16 g_woh[EMB * EMB],  g_wol[EMB * EMB];
__device__ __nv_bfloat16 g_oh[T_SEQ * EMB], g_ol[T_SEQ * EMB];

// attention K/V bf16 hi/lo (K: [kv][t][d], V transposed: [kv][d][t])
__device__ __nv_bfloat16 g_kh[NKV * T_SEQ * HD], g_kl[NKV * T_SEQ * HD];
__device__ __nv_bfloat16 g_vh[NKV * HD * T_SEQ], g_vl[NKV * HD * T_SEQ];

// one extern-shared buffer shared by all dynamic-smem kernels
extern __shared__ char dsm_raw[];

// ---------------------------------------------------------------------------
// Decode rw_allow_blocks robustly (bool/int8 vs int32 vs float32).
// ---------------------------------------------------------------------------
__global__ void decode_mask_kernel(const void* p) {
    __shared__ int cnt0, cnt123;
    int tid = threadIdx.x;
    if (tid == 0) { cnt0 = 0; cnt123 = 0; }
    __syncthreads();
    const unsigned char* b = (const unsigned char*)p;
    int l0 = 0, l123 = 0;
    for (int i = tid; i < 1024; i += 256) {
        if (b[i]) { if ((i & 3) == 0) l0++; else l123++; }
    }
    atomicAdd(&cnt0, l0);
    atomicAdd(&cnt123, l123);
    __syncthreads();
    if (cnt123 == 0) {
        const int* a = (const int*)p;
        for (int i = tid; i < 1024; i += 256) g_allow[i] = (a[i] != 0);
    } else if (cnt0 == 0) {
        const float* a = (const float*)p;
        for (int i = tid; i < 1024; i += 256) g_allow[i] = (a[i] != 0.0f);
    } else {
        for (int i = tid; i < 1024; i += 256) g_allow[i] = (b[i] != 0);
    }
}

// ---------------------------------------------------------------------------
// Shared helpers
// ---------------------------------------------------------------------------
#define MMA_BF16(d, a0, a1, a2, a3, b0, b1)                                   \
    asm volatile(                                                             \
        "mma.sync.aligned.m16n8k16.row.col.f32.bf16.bf16.f32 "                \
        "{%0,%1,%2,%3}, {%4,%5,%6,%7}, {%8,%9}, {%0,%1,%2,%3};"               \
        : "+f"(d[0]), "+f"(d[1]), "+f"(d[2]), "+f"(d[3])                      \
        : "r"(a0), "r"(a1), "r"(a2), "r"(a3), "r"(b0), "r"(b1))

#define LDSM_X4(R0, R1, R2, R3, ADDR)                                         \
    asm volatile("ldmatrix.sync.aligned.m8n8.x4.shared.b16 {%0,%1,%2,%3}, [%4];" \
        : "=r"(R0), "=r"(R1), "=r"(R2), "=r"(R3) : "r"(ADDR))

#define LDSM_X2(R0, R1, ADDR)                                                 \
    asm volatile("ldmatrix.sync.aligned.m8n8.x2.shared.b16 {%0,%1}, [%2];"    \
        : "=r"(R0), "=r"(R1) : "r"(ADDR))

__device__ __forceinline__ void cp16(uint32_t saddr, const void* g) {
    asm volatile("cp.async.cg.shared.global [%0], [%1], 16;" :: "r"(saddr), "l"(g));
}
__device__ __forceinline__ void cp_commit() {
    asm volatile("cp.async.commit_group;" ::: "memory");
}

__device__ __forceinline__ void cvt2(float2 f, uint32_t& hi, uint32_t& lo) {
    __nv_bfloat162 h = __floats2bfloat162_rn(f.x, f.y);
    hi = *reinterpret_cast<uint32_t*>(&h);
    __nv_bfloat162 l = __floats2bfloat162_rn(f.x - __bfloat162float(h.x),
                                             f.y - __bfloat162float(h.y));
    lo = *reinterpret_cast<uint32_t*>(&l);
}

__device__ __forceinline__ uint32_t smem_u32(const void* p) {
    return (uint32_t)__cvta_generic_to_shared(p);
}

// fp32 -> bf16 hi/lo, 4 elements per thread
__device__ __forceinline__ void cvt_body(const float* __restrict__ src,
                                         __nv_bfloat16* __restrict__ h,
                                         __nv_bfloat16* __restrict__ l, int i) {
    float4 v = ((const float4*)src)[i];
    uint32_t h0, l0, h1, l1;
    cvt2(make_float2(v.x, v.y), h0, l0);
    cvt2(make_float2(v.z, v.w), h1, l1);
    ((uint2*)h)[i] = make_uint2(h0, h1);
    ((uint2*)l)[i] = make_uint2(l0, l1);
}

__global__ void cvt_hilo(const float* __restrict__ src,
                         __nv_bfloat16* __restrict__ h,
                         __nv_bfloat16* __restrict__ l, int n4) {
    int i = blockIdx.x * blockDim.x + threadIdx.x;
    if (i < n4) cvt_body(src, h, l, i);
}

// fused conversion of three tensors (Wk, Wv, Wo)
__global__ void cvt_hilo3(const float* s0, __nv_bfloat16* h0, __nv_bfloat16* l0, int n0,
                          const float* s1, __nv_bfloat16* h1, __nv_bfloat16* l1, int n1,
                          const float* s2, __nv_bfloat16* h2, __nv_bfloat16* l2, int n2) {
    int i = blockIdx.x * blockDim.x + threadIdx.x;
    if (i < n0) { cvt_body(s0, h0, l0, i); return; }
    i -= n0;
    if (i < n1) { cvt_body(s1, h1, l1, i); return; }
    i -= n1;
    if (i < n2) cvt_body(s2, h2, l2, i);
}

// ---------------------------------------------------------------------------
// GEMM (best known): C = A * B^T, pre-split bf16 hi/lo, ldmatrix frags.
// Block 128x128, BK=32, dynamic smem (2 stages x 40KB), 2 CTAs/SM.
// ---------------------------------------------------------------------------
#define TPADH      40
#define G3_ROW_B   (TPADH * 2)              // 80 bytes
#define G3_TILE_B  (128 * G3_ROW_B)         // 10240
#define G3_STAGE_B (4 * G3_TILE_B)          // 40960
#define G3_SMEM    (2 * G3_STAGE_B)         // 81920

__device__ __forceinline__ void gemm3_core(
    const __nv_bfloat16* __restrict__ Ah, const __nv_bfloat16* __restrict__ Al,
    const __nv_bfloat16* __restrict__ Bh, const __nv_bfloat16* __restrict__ Bl,
    float* __restrict__ C, int K, int ldc, int m0, int n0)
{
    uint32_t sbase = smem_u32(dsm_raw);

    int tid  = threadIdx.x;
    int warp = tid >> 5;
    int lane = tid & 31;
    int wm = warp & 1;
    int wn = warp >> 1;
    int qr = lane >> 2;
    int qc2 = (lane & 3) * 2;

    float acc[4][4][4];
#pragma unroll
    for (int i = 0; i < 4; i++)
#pragma unroll
        for (int j = 0; j < 4; j++)
#pragma unroll
            for (int e = 0; e < 4; e++) acc[i][j][e] = 0.0f;

    const __nv_bfloat16* srcs[4];
    srcs[0] = Ah + (size_t)m0 * K;
    srcs[1] = Al + (size_t)m0 * K;
    srcs[2] = Bh + (size_t)n0 * K;
    srcs[3] = Bl + (size_t)n0 * K;

    int arow = wm * 64 + (lane & 7) + ((lane >> 3) & 1) * 8;
    uint32_t aOff = arow * G3_ROW_B + ((lane >> 4) & 1) * 16;
    int brow = wn * 32 + (lane & 7);
    uint32_t bOff = brow * G3_ROW_B + ((lane >> 3) & 1) * 16;

    const int NITER = K / 32;

    {
        uint32_t sb = sbase;
#pragma unroll
        for (int t = 0; t < 8; t++) {
            int id = t * 256 + tid;
            int tile = id >> 9;
            int row  = (id >> 2) & 127;
            int c    = id & 3;
            cp16(sb + tile * G3_TILE_B + row * G3_ROW_B + c * 16,
                 srcs[tile] + (size_t)row * K + c * 8);
        }
        cp_commit();
    }

    for (int it = 0; it < NITER; it++) {
        if (it + 1 < NITER) {
            int k0 = (it + 1) * 32;
            uint32_t sb = sbase + ((it + 1) & 1) * G3_STAGE_B;
#pragma unroll
            for (int t = 0; t < 8; t++) {
                int id = t * 256 + tid;
                int tile = id >> 9;
                int row  = (id >> 2) & 127;
                int c    = id & 3;
                cp16(sb + tile * G3_TILE_B + row * G3_ROW_B + c * 16,
                     srcs[tile] + (size_t)row * K + k0 + c * 8);
            }
            cp_commit();
            asm volatile("cp.async.wait_group 1;" ::: "memory");
        } else {
            asm volatile("cp.async.wait_group 0;" ::: "memory");
        }
        __syncthreads();

        uint32_t sb = sbase + (it & 1) * G3_STAGE_B;
        uint32_t tAh = sb, tAl = sb + G3_TILE_B;
        uint32_t tBh = sb + 2 * G3_TILE_B, tBl = sb + 3 * G3_TILE_B;

#pragma unroll
        for (int k1 = 0; k1 < 2; k1++) {
            uint32_t ko = k1 * 32;
            uint32_t ah[4][4], al[4][4];
#pragma unroll
            for (int mi = 0; mi < 4; mi++) {
                uint32_t off = aOff + mi * (16 * G3_ROW_B) + ko;
                LDSM_X4(ah[mi][0], ah[mi][1], ah[mi][2], ah[mi][3], tAh + off);
                LDSM_X4(al[mi][0], al[mi][1], al[mi][2], al[mi][3], tAl + off);
            }
#pragma unroll
            for (int ni = 0; ni < 4; ni++) {
                uint32_t off = bOff + ni * (8 * G3_ROW_B) + ko;
                uint32_t bh0, bh1, bl0, bl1;
                LDSM_X2(bh0, bh1, tBh + off);
                LDSM_X2(bl0, bl1, tBl + off);
#pragma unroll
                for (int mi = 0; mi < 4; mi++) {
                    MMA_BF16(acc[mi][ni], ah[mi][0], ah[mi][1], ah[mi][2], ah[mi][3], bh0, bh1);
                    MMA_BF16(acc[mi][ni], ah[mi][0], ah[mi][1], ah[mi][2], ah[mi][3], bl0, bl1);
                    MMA_BF16(acc[mi][ni], al[mi][0], al[mi][1], al[mi][2], al[mi][3], bh0, bh1);
                }
            }
        }
        __syncthreads();
    }

#pragma unroll
    for (int mi = 0; mi < 4; mi++) {
#pragma unroll
        for (int ni = 0; ni < 4; ni++) {
            int r = m0 + wm * 64 + mi * 16 + qr;
            int cidx = n0 + wn * 32 + ni * 8 + qc2;
            *(float2*)&C[(size_t)r * ldc + cidx] =
                make_float2(acc[mi][ni][0], acc[mi][ni][1]);
            *(float2*)&C[(size_t)(r + 8) * ldc + cidx] =
                make_float2(acc[mi][ni][2], acc[mi][ni][3]);
        }
    }
}

__global__ __launch_bounds__(256, 2)
void qkv_gemm() {
    int bx = blockIdx.x;
    int m0 = blockIdx.y * 128;
    if (bx < 16)
        gemm3_core(g_hsh, g_hsl, g_wqh, g_wql, g_q, EMB, EMB, m0, bx * 128);
    else if (bx < 20)
        gemm3_core(g_hsh, g_hsl, g_wkh, g_wkl, g_k, EMB, KVD, m0, (bx - 16) * 128);
    else
        gemm3_core(g_hsh, g_hsl, g_wvh, g_wvl, g_v, EMB, KVD, m0, (bx - 20) * 128);
}

__global__ __launch_bounds__(256, 2)
void out_gemm(float* __restrict__ out) {
    gemm3_core(g_oh, g_ol, g_woh, g_wol, out, EMB, EMB,
               blockIdx.y * 128, blockIdx.x * 128);
}

// ---------------------------------------------------------------------------
// RoPE applied in-place to q and k.
// ---------------------------------------------------------------------------
__global__ void rope_kernel(const float* __restrict__ cosb, const float* __restrict__ sinb) {
    int idx = blockIdx.x * blockDim.x + threadIdx.x;
    const int total = T_SEQ * (NH + NKV) * 32;
    if (idx >= total) return;
    int d = idx & 31;
    int rest = idx >> 5;
    int head = rest % (NH + NKV);
    int t = rest / (NH + NKV);
    float c0 = cosb[t * HD + d];
    float s0 = sinb[t * HD + d];
    float c1 = cosb[t * HD + d + 32];
    float s1 = sinb[t * HD + d + 32];
    float* base = (head < NH) ? (g_q + ((size_t)t * NH + head) * HD)
                              : (g_k + ((size_t)t * NKV + (head - NH)) * HD);
    float x0 = base[d];
    float x1 = base[d + 32];
    base[d]      = x0 * c0 - x1 * s0;
    base[d + 32] = x1 * c1 + x0 * s1;
}

// ---------------------------------------------------------------------------
// Fused prep: K -> bf16 hi/lo [kv][t][d]; V -> transposed [kv][d][t].
// ---------------------------------------------------------------------------
__global__ void prep_kv_kernel() {
    const int NK = NKV * T_SEQ * HD;
    int o = blockIdx.x * blockDim.x + threadIdx.x;
    if (o < NK) {
        int d  = o & 63;
        int t  = (o >> 6) & (T_SEQ - 1);
        int kv = o >> 17;
        float v = g_k[((size_t)t * NKV + kv) * HD + d];
        __nv_bfloat16 h = __float2bfloat16(v);
        g_kh[o] = h;
        g_kl[o] = __float2bfloat16(v - __bfloat162float(h));
    } else {
        o -= NK;
        if (o >= NK) return;
        int t  = o & (T_SEQ - 1);
        int d  = (o >> 11) & 63;
        int kv = o >> 17;
        float v = g_v[((size_t)t * NKV + kv) * HD + d];
        __nv_bfloat16 h = __float2bfloat16(v);
        g_vh[o] = h;
        g_vl[o] = __float2bfloat16(v - __bfloat162float(h));
    }
}

// ---------------------------------------------------------------------------
// MMA flash attention: 2 heads per CTA (shared K/V tiles), double-buffered kb
// tiles, ldmatrix frag loads, exp2 softmax.
// ---------------------------------------------------------------------------
#define TSTR  72
#define TSTRB (TSTR * 2)                 // 144 bytes per tile row
#define ATT_TILE   (64 * TSTR)
#define ATT_TILE_B (ATT_TILE * 2)
#define ATT_STAGE  (4 * ATT_TILE)
#define ATT_STAGE_B (ATT_STAGE * 2)
#define ATT_SMEM   (2 * ATT_STAGE_B)

__device__ __forceinline__ void att_issue_loads(__nv_bfloat16* att_dsm,
                                                int stage, int kb, int kv, int tid) {
    uint32_t base = smem_u32(att_dsm) + stage * ATT_STAGE_B;
#pragma unroll
    for (int t = 0; t < 16; t++) {
        int id   = t * 128 + tid;
        int tile = id >> 9;
        int row  = (id >> 3) & 63;
        int ch   = id & 7;
        const __nv_bfloat16* src;
        if (tile == 0)
            src = g_kh + (((size_t)kv * T_SEQ + kb * 64 + row) * HD + ch * 8);
        else if (tile == 1)
            src = g_kl + (((size_t)kv * T_SEQ + kb * 64 + row) * HD + ch * 8);
        else if (tile == 2)
            src = g_vh + (((size_t)kv * HD + row) * T_SEQ + kb * 64 + ch * 8);
        else
            src = g_vl + (((size_t)kv * HD + row) * T_SEQ + kb * 64 + ch * 8);
        cp16(base + tile * ATT_TILE_B + row * TSTRB + ch * 16, src);
    }
    cp_commit();
}

__global__ __launch_bounds__(128)
void attn_mma_kernel() {
    __nv_bfloat16* att_dsm = (__nv_bfloat16*)dsm_raw;
    int hp = blockIdx.x;               // head pair 0..15
    int qb = blockIdx.y;
    int h0 = hp * 2;
    int kv = h0 >> 2;
    int tid  = threadIdx.x;
    int w    = tid >> 5;
    int lane = tid & 31;
    int qr   = lane >> 2;
    int qc2  = (lane & 3) * 2;
    int rowA = w * 16 + qr;

    // stage Q for both heads (fp32, scale = 0.125*log2e), build A-frags
    const float QSC = 0.125f * 1.4426950408889634f;
    float* sQ = (float*)att_dsm;       // head hh at offset hh*64*68 floats
    for (int i = tid; i < 2 * 64 * 16; i += 128) {
        int hh  = i >> 10;
        int j   = i & 1023;
        int row = j >> 4;
        int c4  = (j & 15) * 4;
        float4 v = *(const float4*)&g_q[(((size_t)qb * 64 + row) * NH + h0 + hh) * HD + c4];
        v.x *= QSC; v.y *= QSC; v.z *= QSC; v.w *= QSC;
        *(float4*)&sQ[hh * (64 * 68) + row * 68 + c4] = v;
    }
    __syncthreads();

    uint32_t qh[2][4][4], ql[2][4][4];
#pragma unroll
    for (int hh = 0; hh < 2; hh++) {
        const float* q = sQ + hh * (64 * 68);
#pragma unroll
        for (int kc = 0; kc < 4; kc++) {
            int k = kc * 16 + qc2;
            cvt2(*(const float2*)&q[rowA * 68 + k],           qh[hh][kc][0], ql[hh][kc][0]);
            cvt2(*(const float2*)&q[(rowA + 8) * 68 + k],     qh[hh][kc][1], ql[hh][kc][1]);
            cvt2(*(const float2*)&q[rowA * 68 + k + 8],       qh[hh][kc][2], ql[hh][kc][2]);
            cvt2(*(const float2*)&q[(rowA + 8) * 68 + k + 8], qh[hh][kc][3], ql[hh][kc][3]);
        }
    }
    __syncthreads();

    float m[2][2], l[2][2];
    float o[2][8][4];
#pragma unroll
    for (int hh = 0; hh < 2; hh++) {
        m[hh][0] = -1e30f; m[hh][1] = -1e30f;
        l[hh][0] = 0.0f;   l[hh][1] = 0.0f;
#pragma unroll
        for (int ni = 0; ni < 8; ni++)
#pragma unroll
            for (int e = 0; e < 4; e++) o[hh][ni][e] = 0.0f;
    }

    uint32_t lanePat = (uint32_t)(lane & 7) * TSTRB + ((lane >> 3) & 1) * 16;
    uint32_t sbase = smem_u32(att_dsm);

    int cur = 0, stage = 0;
    att_issue_loads(att_dsm, 0, 0, kv, tid);

    while (cur < NBLK) {
        int nxt = cur + 1;
        while (nxt < NBLK) {
            if (g_allow[qb * NBLK + nxt] || (nxt < 4) ||
                (nxt <= qb && nxt + 4 >= qb)) break;
            nxt++;
        }
        if (nxt < NBLK) {
            att_issue_loads(att_dsm, stage ^ 1, nxt, kv, tid);
            asm volatile("cp.async.wait_group 1;" ::: "memory");
        } else {
            asm volatile("cp.async.wait_group 0;" ::: "memory");
        }
        __syncthreads();

        int kb = cur;
        int ba = g_allow[qb * NBLK + kb];
        uint32_t sb = sbase + stage * ATT_STAGE_B;
        uint32_t aKh = sb + lanePat;
        uint32_t aKl = aKh + ATT_TILE_B;
        uint32_t aVh = sb + 2 * ATT_TILE_B + lanePat;
        uint32_t aVl = aVh + ATT_TILE_B;

        int qi0 = qb * 64 + rowA;
        int qi1 = qi0 + 8;

#pragma unroll
        for (int hh = 0; hh < 2; hh++) {
            // ---- S = Q K^T ----
            float s[8][4];
#pragma unroll
            for (int ni = 0; ni < 8; ni++) {
#pragma unroll
                for (int e = 0; e < 4; e++) s[ni][e] = 0.0f;
#pragma unroll
                for (int kc = 0; kc < 4; kc++) {
                    uint32_t off = ni * (8 * TSTRB) + kc * 32;
                    uint32_t bh0, bh1, bl0, bl1;
                    LDSM_X2(bh0, bh1, aKh + off);
                    LDSM_X2(bl0, bl1, aKl + off);
                    MMA_BF16(s[ni], qh[hh][kc][0], qh[hh][kc][1], qh[hh][kc][2], qh[hh][kc][3], bh0, bh1);
                    MMA_BF16(s[ni], qh[hh][kc][0], qh[hh][kc][1], qh[hh][kc][2], qh[hh][kc][3], bl0, bl1);
                    MMA_BF16(s[ni], ql[hh][kc][0], ql[hh][kc][1], ql[hh][kc][2], ql[hh][kc][3], bh0, bh1);
                }
            }

            // ---- mask ----
#pragma unroll
            for (int ni = 0; ni < 8; ni++) {
                int col = kb * 64 + ni * 8 + qc2;
#pragma unroll
                for (int e = 0; e < 4; e++) {
                    int kj = col + (e & 1);
                    int qi = (e < 2) ? qi0 : qi1;
                    bool ok = ba || (kj < WIN) || (kj <= qi && kj + (WIN - 1) >= qi);
                    if (!ok) s[ni][e] = -1e30f;
                }
            }

            // ---- online softmax (base 2) ----
            float mb0 = -1e30f, mb1 = -1e30f;
#pragma unroll
            for (int ni = 0; ni < 8; ni++) {
                mb0 = fmaxf(mb0, fmaxf(s[ni][0], s[ni][1]));
                mb1 = fmaxf(mb1, fmaxf(s[ni][2], s[ni][3]));
            }
            mb0 = fmaxf(mb0, __shfl_xor_sync(0xFFFFFFFF, mb0, 1));
            mb0 = fmaxf(mb0, __shfl_xor_sync(0xFFFFFFFF, mb0, 2));
            mb1 = fmaxf(mb1, __shfl_xor_sync(0xFFFFFFFF, mb1, 1));
            mb1 = fmaxf(mb1, __shfl_xor_sync(0xFFFFFFFF, mb1, 2));

            float mn0 = fmaxf(m[hh][0], mb0), mn1 = fmaxf(m[hh][1], mb1);
            float sc0 = exp2f(m[hh][0] - mn0), sc1 = exp2f(m[hh][1] - mn1);
            m[hh][0] = mn0; m[hh][1] = mn1;
            l[hh][0] *= sc0; l[hh][1] *= sc1;
#pragma unroll
            for (int ni = 0; ni < 8; ni++) {
                o[hh][ni][0] *= sc0; o[hh][ni][1] *= sc0;
                o[hh][ni][2] *= sc1; o[hh][ni][3] *= sc1;
            }

#pragma unroll
            for (int ni = 0; ni < 8; ni++) {
                s[ni][0] = exp2f(s[ni][0] - mn0);
                s[ni][1] = exp2f(s[ni][1] - mn0);
                s[ni][2] = exp2f(s[ni][2] - mn1);
                s[ni][3] = exp2f(s[ni][3] - mn1);
                l[hh][0] += s[ni][0] + s[ni][1];
                l[hh][1] += s[ni][2] + s[ni][3];
            }

            // ---- O += P V ----
#pragma unroll
            for (int kc = 0; kc < 4; kc++) {
                uint32_t ah[4], al[4];
                cvt2(make_float2(s[2 * kc][0],     s[2 * kc][1]),     ah[0], al[0]);
                cvt2(make_float2(s[2 * kc][2],     s[2 * kc][3]),     ah[1], al[1]);
                cvt2(make_float2(s[2 * kc + 1][0], s[2 * kc + 1][1]), ah[2], al[2]);
                cvt2(make_float2(s[2 * kc + 1][2], s[2 * kc + 1][3]), ah[3], al[3]);
#pragma unroll
                for (int ni = 0; ni < 8; ni++) {
                    uint32_t off = ni * (8 * TSTRB) + kc * 32;
                    uint32_t bh0, bh1, bl0, bl1;
                    LDSM_X2(bh0, bh1, aVh + off);
                    LDSM_X2(bl0, bl1, aVl + off);
                    MMA_BF16(o[hh][ni], ah[0], ah[1], ah[2], ah[3], bh0, bh1);
                    MMA_BF16(o[hh][ni], ah[0], ah[1], ah[2], ah[3], bl0, bl1);
                    MMA_BF16(o[hh][ni], al[0], al[1], al[2], al[3], bh0, bh1);
                }
            }
        }
        __syncthreads();
        cur = nxt;
        stage ^= 1;
    }

    // finalize: reduce l, normalize, write bf16 hi/lo for both heads
    int qi0 = qb * 64 + rowA;
#pragma unroll
    for (int hh = 0; hh < 2; hh++) {
        float l0 = l[hh][0], l1 = l[hh][1];
        l0 += __shfl_xor_sync(0xFFFFFFFF, l0, 1);
        l0 += __shfl_xor_sync(0xFFFFFFFF, l0, 2);
        l1 += __shfl_xor_sync(0xFFFFFFFF, l1, 1);
        l1 += __shfl_xor_sync(0xFFFFFFFF, l1, 2);
        float inv0 = 1.0f / l0, inv1 = 1.0f / l1;
        int hcol = (h0 + hh) * HD;
#pragma unroll
        for (int ni = 0; ni < 8; ni++) {
            int d = ni * 8 + qc2;
            uint32_t hi, lo;
            cvt2(make_float2(o[hh][ni][0] * inv0, o[hh][ni][1] * inv0), hi, lo);
            int idx0 = ((size_t)qi0 * EMB + hcol + d) >> 1;
            ((uint32_t*)g_oh)[idx0] = hi;
            ((uint32_t*)g_ol)[idx0] = lo;
            cvt2(make_float2(o[hh][ni][2] * inv1, o[hh][ni][3] * inv1), hi, lo);
            int idx1 = ((size_t)(qi0 + 8) * EMB + hcol + d) >> 1;
            ((uint32_t*)g_oh)[idx1] = hi;
            ((uint32_t*)g_ol)[idx1] = lo;
        }
    }
}

// ---------------------------------------------------------------------------
extern "C" void kernel_launch(void* const* d_in, const int* in_sizes, int n_in,
                              void* d_out, int out_size) {
    const float* hs   = (const float*)d_in[0];
    const float* cosb = (const float*)d_in[1];
    const float* sinb = (const float*)d_in[2];
    const float* Wq   = (const float*)d_in[3];
    const float* Wk   = (const float*)d_in[4];
    const float* Wv   = (const float*)d_in[5];
    const float* Wo   = (const float*)d_in[6];
    const void*  allow = d_in[7];
    float* out = (float*)d_out;

    __nv_bfloat16 *hsh, *hsl, *wqh, *wql, *wkh, *wkl, *wvh, *wvl, *woh, *wol;
    cudaGetSymbolAddress((void**)&hsh, g_hsh);
    cudaGetSymbolAddress((void**)&hsl, g_hsl);
    cudaGetSymbolAddress((void**)&wqh, g_wqh);
    cudaGetSymbolAddress((void**)&wql, g_wql);
    cudaGetSymbolAddress((void**)&wkh, g_wkh);
    cudaGetSymbolAddress((void**)&wkl, g_wkl);
    cudaGetSymbolAddress((void**)&wvh, g_wvh);
    cudaGetSymbolAddress((void**)&wvl, g_wvl);
    cudaGetSymbolAddress((void**)&woh, g_woh);
    cudaGetSymbolAddress((void**)&wol, g_wol);

    cudaFuncSetAttribute(attn_mma_kernel,
                         cudaFuncAttributeMaxDynamicSharedMemorySize, ATT_SMEM);
    cudaFuncSetAttribute(qkv_gemm,
                         cudaFuncAttributeMaxDynamicSharedMemorySize, G3_SMEM);
    cudaFuncSetAttribute(out_gemm,
                         cudaFuncAttributeMaxDynamicSharedMemorySize, G3_SMEM);

    // launch 0-2: conversions (qkv_gemm lands at index 3 = ncu capture slot)
    {
        int n4 = T_SEQ * EMB / 4;
        cvt_hilo<<<(n4 + 255) / 256, 256>>>(hs, hsh, hsl, n4);
        n4 = EMB * EMB / 4;
        cvt_hilo<<<(n4 + 255) / 256, 256>>>(Wq, wqh, wql, n4);
        int nk = KVD * EMB / 4, no = EMB * EMB / 4;
        int tot = 2 * nk + no;
        cvt_hilo3<<<(tot + 255) / 256, 256>>>(Wk, wkh, wkl, nk,
                                              Wv, wvh, wvl, nk,
                                              Wo, woh, wol, no);
    }

    // launch 3: fused QKV projection (ncu capture target)
    qkv_gemm<<<dim3(24, T_SEQ / 128), 256, G3_SMEM>>>();

    // RoPE (q, k in place)
    {
        int total = T_SEQ * (NH + NKV) * 32;
        rope_kernel<<<(total + 255) / 256, 256>>>(cosb, sinb);
    }

    // Pre-convert K (post-RoPE) and V for attention (fused)
    prep_kv_kernel<<<(2 * NKV * T_SEQ * HD + 255) / 256, 256>>>();

    // Mask decode
    decode_mask_kernel<<<1, 256>>>(allow);

    // MMA flash attention (2 heads per CTA)
    attn_mma_kernel<<<dim3(NH / 2, NBLK), 128, ATT_SMEM>>>();

    // Output projection
    out_gemm<<<dim3(EMB / 128, T_SEQ / 128), 256, G3_SMEM>>>(out);
}

// round 13
// speedup vs baseline: 1.0708x; 1.0708x over previous
#include <cuda_runtime.h>
#include <cuda_bf16.h>
#include <math.h>
#include <stdint.h>

// Problem constants (fixed by setup_inputs)
#define T_SEQ 2048
#define EMB   2048
#define NH    32
#define NKV   8
#define HD    64
#define NBLK  32
#define WIN   256
#define KVD   (NKV * HD)   // 512

// fp32 scratch
__device__ float g_q[T_SEQ * NH * HD];     // [t][h][d]
__device__ float g_k[T_SEQ * NKV * HD];    // [t][kv][d]
__device__ float g_v[T_SEQ * NKV * HD];
__device__ int   g_allow[NBLK * NBLK];

// bf16 hi/lo pre-converted operands
__device__ __nv_bfloat16 g_hsh[T_SEQ * EMB], g_hsl[T_SEQ * EMB];
__device__ __nv_bfloat16 g_wqh[EMB * EMB],  g_wql[EMB * EMB];
__device__ __nv_bfloat16 g_wkh[KVD * EMB],  g_wkl[KVD * EMB];
__device__ __nv_bfloat16 g_wvh[KVD * EMB],  g_wvl[KVD * EMB];
__device__ __nv_bfloat16 g_woh[EMB * EMB],  g_wol[EMB * EMB];
__device__ __nv_bfloat16 g_oh[T_SEQ * EMB], g_ol[T_SEQ * EMB];

// attention K/V bf16 hi/lo (K: [kv][t][d], V transposed: [kv][d][t])
__device__ __nv_bfloat16 g_kh[NKV * T_SEQ * HD], g_kl[NKV * T_SEQ * HD];
__device__ __nv_bfloat16 g_vh[NKV * HD * T_SEQ], g_vl[NKV * HD * T_SEQ];

// one extern-shared buffer shared by all dynamic-smem kernels
extern __shared__ char dsm_raw[];

// ---------------------------------------------------------------------------
// Decode rw_allow_blocks robustly (bool/int8 vs int32 vs float32).
// ---------------------------------------------------------------------------
__global__ void decode_mask_kernel(const void* p) {
    __shared__ int cnt0, cnt123;
    int tid = threadIdx.x;
    if (tid == 0) { cnt0 = 0; cnt123 = 0; }
    __syncthreads();
    const unsigned char* b = (const unsigned char*)p;
    int l0 = 0, l123 = 0;
    for (int i = tid; i < 1024; i += 256) {
        if (b[i]) { if ((i & 3) == 0) l0++; else l123++; }
    }
    atomicAdd(&cnt0, l0);
    atomicAdd(&cnt123, l123);
    __syncthreads();
    if (cnt123 == 0) {
        const int* a = (const int*)p;
        for (int i = tid; i < 1024; i += 256) g_allow[i] = (a[i] != 0);
    } else if (cnt0 == 0) {
        const float* a = (const float*)p;
        for (int i = tid; i < 1024; i += 256) g_allow[i] = (a[i] != 0.0f);
    } else {
        for (int i = tid; i < 1024; i += 256) g_allow[i] = (b[i] != 0);
    }
}

// ---------------------------------------------------------------------------
// Shared helpers
// ---------------------------------------------------------------------------
#define MMA_BF16(d, a0, a1, a2, a3, b0, b1)                                   \
    asm volatile(                                                             \
        "mma.sync.aligned.m16n8k16.row.col.f32.bf16.bf16.f32 "                \
        "{%0,%1,%2,%3}, {%4,%5,%6,%7}, {%8,%9}, {%0,%1,%2,%3};"               \
        : "+f"(d[0]), "+f"(d[1]), "+f"(d[2]), "+f"(d[3])                      \
        : "r"(a0), "r"(a1), "r"(a2), "r"(a3), "r"(b0), "r"(b1))

#define LDSM_X4(R0, R1, R2, R3, ADDR)                                         \
    asm volatile("ldmatrix.sync.aligned.m8n8.x4.shared.b16 {%0,%1,%2,%3}, [%4];" \
        : "=r"(R0), "=r"(R1), "=r"(R2), "=r"(R3) : "r"(ADDR))

#define LDSM_X2(R0, R1, ADDR)                                                 \
    asm volatile("ldmatrix.sync.aligned.m8n8.x2.shared.b16 {%0,%1}, [%2];"    \
        : "=r"(R0), "=r"(R1) : "r"(ADDR))

__device__ __forceinline__ void cp16(uint32_t saddr, const void* g) {
    asm volatile("cp.async.cg.shared.global [%0], [%1], 16;" :: "r"(saddr), "l"(g));
}
__device__ __forceinline__ void cp_commit() {
    asm volatile("cp.async.commit_group;" ::: "memory");
}

__device__ __forceinline__ void cvt2(float2 f, uint32_t& hi, uint32_t& lo) {
    __nv_bfloat162 h = __floats2bfloat162_rn(f.x, f.y);
    hi = *reinterpret_cast<uint32_t*>(&h);
    __nv_bfloat162 l = __floats2bfloat162_rn(f.x - __bfloat162float(h.x),
                                             f.y - __bfloat162float(h.y));
    lo = *reinterpret_cast<uint32_t*>(&l);
}

__device__ __forceinline__ uint32_t smem_u32(const void* p) {
    return (uint32_t)__cvta_generic_to_shared(p);
}

// fp32 -> bf16 hi/lo, 4 elements per thread
__device__ __forceinline__ void cvt_body(const float* __restrict__ src,
                                         __nv_bfloat16* __restrict__ h,
                                         __nv_bfloat16* __restrict__ l, int i) {
    float4 v = ((const float4*)src)[i];
    uint32_t h0, l0, h1, l1;
    cvt2(make_float2(v.x, v.y), h0, l0);
    cvt2(make_float2(v.z, v.w), h1, l1);
    ((uint2*)h)[i] = make_uint2(h0, h1);
    ((uint2*)l)[i] = make_uint2(l0, l1);
}

__global__ void cvt_hilo(const float* __restrict__ src,
                         __nv_bfloat16* __restrict__ h,
                         __nv_bfloat16* __restrict__ l, int n4) {
    int i = blockIdx.x * blockDim.x + threadIdx.x;
    if (i < n4) cvt_body(src, h, l, i);
}

// fused conversion of three tensors (Wk, Wv, Wo)
__global__ void cvt_hilo3(const float* s0, __nv_bfloat16* h0, __nv_bfloat16* l0, int n0,
                          const float* s1, __nv_bfloat16* h1, __nv_bfloat16* l1, int n1,
                          const float* s2, __nv_bfloat16* h2, __nv_bfloat16* l2, int n2) {
    int i = blockIdx.x * blockDim.x + threadIdx.x;
    if (i < n0) { cvt_body(s0, h0, l0, i); return; }
    i -= n0;
    if (i < n1) { cvt_body(s1, h1, l1, i); return; }
    i -= n1;
    if (i < n2) cvt_body(s2, h2, l2, i);
}

// ---------------------------------------------------------------------------
// GEMM: C = A * B^T, pre-split bf16 hi/lo, ldmatrix frags, B-frag register
// double-buffer. Block 128x128, BK=32, 2 smem stages, 2 CTAs/SM.
// ---------------------------------------------------------------------------
#define TPADH      40
#define G3_ROW_B   (TPADH * 2)              // 80 bytes
#define G3_TILE_B  (128 * G3_ROW_B)         // 10240
#define G3_STAGE_B (4 * G3_TILE_B)          // 40960
#define G3_SMEM    (2 * G3_STAGE_B)         // 81920

__device__ __forceinline__ void gemm3_core(
    const __nv_bfloat16* __restrict__ Ah, const __nv_bfloat16* __restrict__ Al,
    const __nv_bfloat16* __restrict__ Bh, const __nv_bfloat16* __restrict__ Bl,
    float* __restrict__ C, int K, int ldc, int m0, int n0)
{
    uint32_t sbase = smem_u32(dsm_raw);

    int tid  = threadIdx.x;
    int warp = tid >> 5;
    int lane = tid & 31;
    int wm = warp & 1;
    int wn = warp >> 1;
    int qr = lane >> 2;
    int qc2 = (lane & 3) * 2;

    float acc[4][4][4];
#pragma unroll
    for (int i = 0; i < 4; i++)
#pragma unroll
        for (int j = 0; j < 4; j++)
#pragma unroll
            for (int e = 0; e < 4; e++) acc[i][j][e] = 0.0f;

    const __nv_bfloat16* srcs[4];
    srcs[0] = Ah + (size_t)m0 * K;
    srcs[1] = Al + (size_t)m0 * K;
    srcs[2] = Bh + (size_t)n0 * K;
    srcs[3] = Bl + (size_t)n0 * K;

    int arow = wm * 64 + (lane & 7) + ((lane >> 3) & 1) * 8;
    uint32_t aOff = arow * G3_ROW_B + ((lane >> 4) & 1) * 16;
    int brow = wn * 32 + (lane & 7);
    uint32_t bOff = brow * G3_ROW_B + ((lane >> 3) & 1) * 16;

    const int NITER = K / 32;

    {
        uint32_t sb = sbase;
#pragma unroll
        for (int t = 0; t < 8; t++) {
            int id = t * 256 + tid;
            int tile = id >> 9;
            int row  = (id >> 2) & 127;
            int c    = id & 3;
            cp16(sb + tile * G3_TILE_B + row * G3_ROW_B + c * 16,
                 srcs[tile] + (size_t)row * K + c * 8);
        }
        cp_commit();
    }

    for (int it = 0; it < NITER; it++) {
        if (it + 1 < NITER) {
            int k0 = (it + 1) * 32;
            uint32_t sb = sbase + ((it + 1) & 1) * G3_STAGE_B;
#pragma unroll
            for (int t = 0; t < 8; t++) {
                int id = t * 256 + tid;
                int tile = id >> 9;
                int row  = (id >> 2) & 127;
                int c    = id & 3;
                cp16(sb + tile * G3_TILE_B + row * G3_ROW_B + c * 16,
                     srcs[tile] + (size_t)row * K + k0 + c * 8);
            }
            cp_commit();
            asm volatile("cp.async.wait_group 1;" ::: "memory");
        } else {
            asm volatile("cp.async.wait_group 0;" ::: "memory");
        }
        __syncthreads();

        uint32_t sb = sbase + (it & 1) * G3_STAGE_B;
        uint32_t tAh = sb, tAl = sb + G3_TILE_B;
        uint32_t tBh = sb + 2 * G3_TILE_B, tBl = sb + 3 * G3_TILE_B;

#pragma unroll
        for (int k1 = 0; k1 < 2; k1++) {
            uint32_t ko = k1 * 32;
            uint32_t ah[4][4], al[4][4];
#pragma unroll
            for (int mi = 0; mi < 4; mi++) {
                uint32_t off = aOff + mi * (16 * G3_ROW_B) + ko;
                LDSM_X4(ah[mi][0], ah[mi][1], ah[mi][2], ah[mi][3], tAh + off);
                LDSM_X4(al[mi][0], al[mi][1], al[mi][2], al[mi][3], tAl + off);
            }
            // B fragments: register double buffer so LDSM for ni+1 overlaps
            // the 12 MMAs of ni.
            uint32_t bh0[2], bh1[2], bl0[2], bl1[2];
            {
                uint32_t off = bOff + ko;
                LDSM_X2(bh0[0], bh1[0], tBh + off);
                LDSM_X2(bl0[0], bl1[0], tBl + off);
            }
#pragma unroll
            for (int ni = 0; ni < 4; ni++) {
                int cb = ni & 1, nb = cb ^ 1;
                if (ni < 3) {
                    uint32_t off = bOff + (ni + 1) * (8 * G3_ROW_B) + ko;
                    LDSM_X2(bh0[nb], bh1[nb], tBh + off);
                    LDSM_X2(bl0[nb], bl1[nb], tBl + off);
                }
#pragma unroll
                for (int mi = 0; mi < 4; mi++) {
                    MMA_BF16(acc[mi][ni], ah[mi][0], ah[mi][1], ah[mi][2], ah[mi][3], bh0[cb], bh1[cb]);
                    MMA_BF16(acc[mi][ni], ah[mi][0], ah[mi][1], ah[mi][2], ah[mi][3], bl0[cb], bl1[cb]);
                    MMA_BF16(acc[mi][ni], al[mi][0], al[mi][1], al[mi][2], al[mi][3], bh0[cb], bh1[cb]);
                }
            }
        }
        __syncthreads();
    }

#pragma unroll
    for (int mi = 0; mi < 4; mi++) {
#pragma unroll
        for (int ni = 0; ni < 4; ni++) {
            int r = m0 + wm * 64 + mi * 16 + qr;
            int cidx = n0 + wn * 32 + ni * 8 + qc2;
            *(float2*)&C[(size_t)r * ldc + cidx] =
                make_float2(acc[mi][ni][0], acc[mi][ni][1]);
            *(float2*)&C[(size_t)(r + 8) * ldc + cidx] =
                make_float2(acc[mi][ni][2], acc[mi][ni][3]);
        }
    }
}

__global__ __launch_bounds__(256, 2)
void qkv_gemm() {
    int bx = blockIdx.x;
    int m0 = blockIdx.y * 128;
    if (bx < 16)
        gemm3_core(g_hsh, g_hsl, g_wqh, g_wql, g_q, EMB, EMB, m0, bx * 128);
    else if (bx < 20)
        gemm3_core(g_hsh, g_hsl, g_wkh, g_wkl, g_k, EMB, KVD, m0, (bx - 16) * 128);
    else
        gemm3_core(g_hsh, g_hsl, g_wvh, g_wvl, g_v, EMB, KVD, m0, (bx - 20) * 128);
}

__global__ __launch_bounds__(256, 2)
void out_gemm(float* __restrict__ out) {
    gemm3_core(g_oh, g_ol, g_woh, g_wol, out, EMB, EMB,
               blockIdx.y * 128, blockIdx.x * 128);
}

// ---------------------------------------------------------------------------
// RoPE applied in-place to q and k.
// ---------------------------------------------------------------------------
__global__ void rope_kernel(const float* __restrict__ cosb, const float* __restrict__ sinb) {
    int idx = blockIdx.x * blockDim.x + threadIdx.x;
    const int total = T_SEQ * (NH + NKV) * 32;
    if (idx >= total) return;
    int d = idx & 31;
    int rest = idx >> 5;
    int head = rest % (NH + NKV);
    int t = rest / (NH + NKV);
    float c0 = cosb[t * HD + d];
    float s0 = sinb[t * HD + d];
    float c1 = cosb[t * HD + d + 32];
    float s1 = sinb[t * HD + d + 32];
    float* base = (head < NH) ? (g_q + ((size_t)t * NH + head) * HD)
                              : (g_k + ((size_t)t * NKV + (head - NH)) * HD);
    float x0 = base[d];
    float x1 = base[d + 32];
    base[d]      = x0 * c0 - x1 * s0;
    base[d + 32] = x1 * c1 + x0 * s1;
}

// ---------------------------------------------------------------------------
// Fused prep: K -> bf16 hi/lo [kv][t][d]; V -> transposed [kv][d][t].
// ---------------------------------------------------------------------------
__global__ void prep_kv_kernel() {
    const int NK = NKV * T_SEQ * HD;
    int o = blockIdx.x * blockDim.x + threadIdx.x;
    if (o < NK) {
        int d  = o & 63;
        int t  = (o >> 6) & (T_SEQ - 1);
        int kv = o >> 17;
        float v = g_k[((size_t)t * NKV + kv) * HD + d];
        __nv_bfloat16 h = __float2bfloat16(v);
        g_kh[o] = h;
        g_kl[o] = __float2bfloat16(v - __bfloat162float(h));
    } else {
        o -= NK;
        if (o >= NK) return;
        int t  = o & (T_SEQ - 1);
        int d  = (o >> 11) & 63;
        int kv = o >> 17;
        float v = g_v[((size_t)t * NKV + kv) * HD + d];
        __nv_bfloat16 h = __float2bfloat16(v);
        g_vh[o] = h;
        g_vl[o] = __float2bfloat16(v - __bfloat162float(h));
    }
}

// ---------------------------------------------------------------------------
// MMA flash attention (R11, best known): 1 head/CTA, double-buffered kb
// tiles, ldmatrix frag loads, exp2 softmax.
// ---------------------------------------------------------------------------
#define TSTR  72
#define TSTRB (TSTR * 2)                 // 144 bytes per tile row
#define ATT_TILE   (64 * TSTR)
#define ATT_TILE_B (ATT_TILE * 2)
#define ATT_STAGE  (4 * ATT_TILE)
#define ATT_STAGE_B (ATT_STAGE * 2)
#define ATT_SMEM   (2 * ATT_STAGE_B)

__device__ __forceinline__ void att_issue_loads(__nv_bfloat16* att_dsm,
                                                int stage, int kb, int kv, int tid) {
    uint32_t base = smem_u32(att_dsm) + stage * ATT_STAGE_B;
#pragma unroll
    for (int t = 0; t < 16; t++) {
        int id   = t * 128 + tid;
        int tile = id >> 9;
        int row  = (id >> 3) & 63;
        int ch   = id & 7;
        const __nv_bfloat16* src;
        if (tile == 0)
            src = g_kh + (((size_t)kv * T_SEQ + kb * 64 + row) * HD + ch * 8);
        else if (tile == 1)
            src = g_kl + (((size_t)kv * T_SEQ + kb * 64 + row) * HD + ch * 8);
        else if (tile == 2)
            src = g_vh + (((size_t)kv * HD + row) * T_SEQ + kb * 64 + ch * 8);
        else
            src = g_vl + (((size_t)kv * HD + row) * T_SEQ + kb * 64 + ch * 8);
        cp16(base + tile * ATT_TILE_B + row * TSTRB + ch * 16, src);
    }
    cp_commit();
}

__global__ __launch_bounds__(128)
void attn_mma_kernel() {
    __nv_bfloat16* att_dsm = (__nv_bfloat16*)dsm_raw;
    int h  = blockIdx.x;
    int qb = blockIdx.y;
    int kv = h >> 2;
    int tid  = threadIdx.x;
    int w    = tid >> 5;
    int lane = tid & 31;
    int qr   = lane >> 2;
    int qc2  = (lane & 3) * 2;
    int rowA = w * 16 + qr;

    const float QSC = 0.125f * 1.4426950408889634f;
    float* sQ = (float*)att_dsm;
    for (int i = tid; i < 64 * 16; i += 128) {
        int row = i >> 4;
        int c4  = (i & 15) * 4;
        float4 v = *(const float4*)&g_q[(((size_t)qb * 64 + row) * NH + h) * HD + c4];
        v.x *= QSC; v.y *= QSC; v.z *= QSC; v.w *= QSC;
        *(float4*)&sQ[row * 68 + c4] = v;
    }
    __syncthreads();

    uint32_t qh[4][4], ql[4][4];
#pragma unroll
    for (int kc = 0; kc < 4; kc++) {
        int k = kc * 16 + qc2;
        cvt2(*(const float2*)&sQ[rowA * 68 + k],           qh[kc][0], ql[kc][0]);
        cvt2(*(const float2*)&sQ[(rowA + 8) * 68 + k],     qh[kc][1], ql[kc][1]);
        cvt2(*(const float2*)&sQ[rowA * 68 + k + 8],       qh[kc][2], ql[kc][2]);
        cvt2(*(const float2*)&sQ[(rowA + 8) * 68 + k + 8], qh[kc][3], ql[kc][3]);
    }
    __syncthreads();

    float m0 = -1e30f, m1 = -1e30f, l0 = 0.0f, l1 = 0.0f;
    float o[8][4];
#pragma unroll
    for (int ni = 0; ni < 8; ni++)
#pragma unroll
        for (int e = 0; e < 4; e++) o[ni][e] = 0.0f;

    uint32_t lanePat = (uint32_t)(lane & 7) * TSTRB + ((lane >> 3) & 1) * 16;
    uint32_t sbase = smem_u32(att_dsm);

    int cur = 0, stage = 0;
    att_issue_loads(att_dsm, 0, 0, kv, tid);

    while (cur < NBLK) {
        int nxt = cur + 1;
        while (nxt < NBLK) {
            if (g_allow[qb * NBLK + nxt] || (nxt < 4) ||
                (nxt <= qb && nxt + 4 >= qb)) break;
            nxt++;
        }
        if (nxt < NBLK) {
            att_issue_loads(att_dsm, stage ^ 1, nxt, kv, tid);
            asm volatile("cp.async.wait_group 1;" ::: "memory");
        } else {
            asm volatile("cp.async.wait_group 0;" ::: "memory");
        }
        __syncthreads();

        int kb = cur;
        int ba = g_allow[qb * NBLK + kb];
        uint32_t sb = sbase + stage * ATT_STAGE_B;
        uint32_t aKh = sb + lanePat;
        uint32_t aKl = aKh + ATT_TILE_B;
        uint32_t aVh = sb + 2 * ATT_TILE_B + lanePat;
        uint32_t aVl = aVh + ATT_TILE_B;

        float s[8][4];
#pragma unroll
        for (int ni = 0; ni < 8; ni++) {
#pragma unroll
            for (int e = 0; e < 4; e++) s[ni][e] = 0.0f;
#pragma unroll
            for (int kc = 0; kc < 4; kc++) {
                uint32_t off = ni * (8 * TSTRB) + kc * 32;
                uint32_t bh0, bh1, bl0, bl1;
                LDSM_X2(bh0, bh1, aKh + off);
                LDSM_X2(bl0, bl1, aKl + off);
                MMA_BF16(s[ni], qh[kc][0], qh[kc][1], qh[kc][2], qh[kc][3], bh0, bh1);
                MMA_BF16(s[ni], qh[kc][0], qh[kc][1], qh[kc][2], qh[kc][3], bl0, bl1);
                MMA_BF16(s[ni], ql[kc][0], ql[kc][1], ql[kc][2], ql[kc][3], bh0, bh1);
            }
        }

        int qi0 = qb * 64 + rowA;
        int qi1 = qi0 + 8;
#pragma unroll
        for (int ni = 0; ni < 8; ni++) {
            int col = kb * 64 + ni * 8 + qc2;
#pragma unroll
            for (int e = 0; e < 4; e++) {
                int kj = col + (e & 1);
                int qi = (e < 2) ? qi0 : qi1;
                bool ok = ba || (kj < WIN) || (kj <= qi && kj + (WIN - 1) >= qi);
                if (!ok) s[ni][e] = -1e30f;
            }
        }

        float mb0 = -1e30f, mb1 = -1e30f;
#pragma unroll
        for (int ni = 0; ni < 8; ni++) {
            mb0 = fmaxf(mb0, fmaxf(s[ni][0], s[ni][1]));
            mb1 = fmaxf(mb1, fmaxf(s[ni][2], s[ni][3]));
        }
        mb0 = fmaxf(mb0, __shfl_xor_sync(0xFFFFFFFF, mb0, 1));
        mb0 = fmaxf(mb0, __shfl_xor_sync(0xFFFFFFFF, mb0, 2));
        mb1 = fmaxf(mb1, __shfl_xor_sync(0xFFFFFFFF, mb1, 1));
        mb1 = fmaxf(mb1, __shfl_xor_sync(0xFFFFFFFF, mb1, 2));

        float mn0 = fmaxf(m0, mb0), mn1 = fmaxf(m1, mb1);
        float sc0 = exp2f(m0 - mn0), sc1 = exp2f(m1 - mn1);
        m0 = mn0; m1 = mn1;
        l0 *= sc0; l1 *= sc1;
#pragma unroll
        for (int ni = 0; ni < 8; ni++) {
            o[ni][0] *= sc0; o[ni][1] *= sc0;
            o[ni][2] *= sc1; o[ni][3] *= sc1;
        }

#pragma unroll
        for (int ni = 0; ni < 8; ni++) {
            s[ni][0] = exp2f(s[ni][0] - m0);
            s[ni][1] = exp2f(s[ni][1] - m0);
            s[ni][2] = exp2f(s[ni][2] - m1);
            s[ni][3] = exp2f(s[ni][3] - m1);
            l0 += s[ni][0] + s[ni][1];
            l1 += s[ni][2] + s[ni][3];
        }

#pragma unroll
        for (int kc = 0; kc < 4; kc++) {
            uint32_t ah[4], al[4];
            cvt2(make_float2(s[2 * kc][0],     s[2 * kc][1]),     ah[0], al[0]);
            cvt2(make_float2(s[2 * kc][2],     s[2 * kc][3]),     ah[1], al[1]);
            cvt2(make_float2(s[2 * kc + 1][0], s[2 * kc + 1][1]), ah[2], al[2]);
            cvt2(make_float2(s[2 * kc + 1][2], s[2 * kc + 1][3]), ah[3], al[3]);
#pragma unroll
            for (int ni = 0; ni < 8; ni++) {
                uint32_t off = ni * (8 * TSTRB) + kc * 32;
                uint32_t bh0, bh1, bl0, bl1;
                LDSM_X2(bh0, bh1, aVh + off);
                LDSM_X2(bl0, bl1, aVl + off);
                MMA_BF16(o[ni], ah[0], ah[1], ah[2], ah[3], bh0, bh1);
                MMA_BF16(o[ni], ah[0], ah[1], ah[2], ah[3], bl0, bl1);
                MMA_BF16(o[ni], al[0], al[1], al[2], al[3], bh0, bh1);
            }
        }
        __syncthreads();
        cur = nxt;
        stage ^= 1;
    }

    l0 += __shfl_xor_sync(0xFFFFFFFF, l0, 1);
    l0 += __shfl_xor_sync(0xFFFFFFFF, l0, 2);
    l1 += __shfl_xor_sync(0xFFFFFFFF, l1, 1);
    l1 += __shfl_xor_sync(0xFFFFFFFF, l1, 2);
    float inv0 = 1.0f / l0, inv1 = 1.0f / l1;

    int qi0 = qb * 64 + rowA;
#pragma unroll
    for (int ni = 0; ni < 8; ni++) {
        int d = ni * 8 + qc2;
        uint32_t hi, lo;
        cvt2(make_float2(o[ni][0] * inv0, o[ni][1] * inv0), hi, lo);
        int idx0 = ((size_t)qi0 * EMB + h * HD + d) >> 1;
        ((uint32_t*)g_oh)[idx0] = hi;
        ((uint32_t*)g_ol)[idx0] = lo;
        cvt2(make_float2(o[ni][2] * inv1, o[ni][3] * inv1), hi, lo);
        int idx1 = ((size_t)(qi0 + 8) * EMB + h * HD + d) >> 1;
        ((uint32_t*)g_oh)[idx1] = hi;
        ((uint32_t*)g_ol)[idx1] = lo;
    }
}

// ---------------------------------------------------------------------------
extern "C" void kernel_launch(void* const* d_in, const int* in_sizes, int n_in,
                              void* d_out, int out_size) {
    const float* hs   = (const float*)d_in[0];
    const float* cosb = (const float*)d_in[1];
    const float* sinb = (const float*)d_in[2];
    const float* Wq   = (const float*)d_in[3];
    const float* Wk   = (const float*)d_in[4];
    const float* Wv   = (const float*)d_in[5];
    const float* Wo   = (const float*)d_in[6];
    const void*  allow = d_in[7];
    float* out = (float*)d_out;

    __nv_bfloat16 *hsh, *hsl, *wqh, *wql, *wkh, *wkl, *wvh, *wvl, *woh, *wol;
    cudaGetSymbolAddress((void**)&hsh, g_hsh);
    cudaGetSymbolAddress((void**)&hsl, g_hsl);
    cudaGetSymbolAddress((void**)&wqh, g_wqh);
    cudaGetSymbolAddress((void**)&wql, g_wql);
    cudaGetSymbolAddress((void**)&wkh, g_wkh);
    cudaGetSymbolAddress((void**)&wkl, g_wkl);
    cudaGetSymbolAddress((void**)&wvh, g_wvh);
    cudaGetSymbolAddress((void**)&wvl, g_wvl);
    cudaGetSymbolAddress((void**)&woh, g_woh);
    cudaGetSymbolAddress((void**)&wol, g_wol);

    cudaFuncSetAttribute(attn_mma_kernel,
                         cudaFuncAttributeMaxDynamicSharedMemorySize, ATT_SMEM);
    cudaFuncSetAttribute(qkv_gemm,
                         cudaFuncAttributeMaxDynamicSharedMemorySize, G3_SMEM);
    cudaFuncSetAttribute(out_gemm,
                         cudaFuncAttributeMaxDynamicSharedMemorySize, G3_SMEM);

    // launch 0-2: conversions (qkv_gemm lands at index 3 = ncu capture slot)
    {
        int n4 = T_SEQ * EMB / 4;
        cvt_hilo<<<(n4 + 255) / 256, 256>>>(hs, hsh, hsl, n4);
        n4 = EMB * EMB / 4;
        cvt_hilo<<<(n4 + 255) / 256, 256>>>(Wq, wqh, wql, n4);
        int nk = KVD * EMB / 4, no = EMB * EMB / 4;
        int tot = 2 * nk + no;
        cvt_hilo3<<<(tot + 255) / 256, 256>>>(Wk, wkh, wkl, nk,
                                              Wv, wvh, wvl, nk,
                                              Wo, woh, wol, no);
    }

    // launch 3: fused QKV projection (ncu capture target)
    qkv_gemm<<<dim3(24, T_SEQ / 128), 256, G3_SMEM>>>();

    // RoPE (q, k in place)
    {
        int total = T_SEQ * (NH + NKV) * 32;
        rope_kernel<<<(total + 255) / 256, 256>>>(cosb, sinb);
    }

    // Pre-convert K (post-RoPE) and V for attention (fused)
    prep_kv_kernel<<<(2 * NKV * T_SEQ * HD + 255) / 256, 256>>>();

    // Mask decode
    decode_mask_kernel<<<1, 256>>>(allow);

    // MMA flash attention (1 head per CTA — best known)
    attn_mma_kernel<<<dim3(NH, NBLK), 128, ATT_SMEM>>>();

    // Output projection
    out_gemm<<<dim3(EMB / 128, T_SEQ / 128), 256, G3_SMEM>>>(out);
}

// round 14
// speedup vs baseline: 1.0759x; 1.0047x over previous
#include <cuda_runtime.h>
#include <cuda_bf16.h>
#include <math.h>
#include <stdint.h>

// Problem constants (fixed by setup_inputs)
#define T_SEQ 2048
#define EMB   2048
#define NH    32
#define NKV   8
#define HD    64
#define NBLK  32
#define WIN   256
#define KVD   (NKV * HD)   // 512

// fp32 scratch (split-K partials: *2 holds K-half 1)
__device__ float g_q[T_SEQ * NH * HD],  g_q2[T_SEQ * NH * HD];
__device__ float g_k[T_SEQ * NKV * HD], g_k2[T_SEQ * NKV * HD];
__device__ float g_v[T_SEQ * NKV * HD], g_v2[T_SEQ * NKV * HD];
__device__ int   g_allow[NBLK * NBLK];

// bf16 hi/lo pre-converted operands
__device__ __nv_bfloat16 g_hsh[T_SEQ * EMB], g_hsl[T_SEQ * EMB];
__device__ __nv_bfloat16 g_wqh[EMB * EMB],  g_wql[EMB * EMB];
__device__ __nv_bfloat16 g_wkh[KVD * EMB],  g_wkl[KVD * EMB];
__device__ __nv_bfloat16 g_wvh[KVD * EMB],  g_wvl[KVD * EMB];
__device__ __nv_bfloat16 g_woh[EMB * EMB],  g_wol[EMB * EMB];
__device__ __nv_bfloat16 g_oh[T_SEQ * EMB], g_ol[T_SEQ * EMB];

// attention K/V bf16 hi/lo (K: [kv][t][d], V transposed: [kv][d][t])
__device__ __nv_bfloat16 g_kh[NKV * T_SEQ * HD], g_kl[NKV * T_SEQ * HD];
__device__ __nv_bfloat16 g_vh[NKV * HD * T_SEQ], g_vl[NKV * HD * T_SEQ];

// one extern-shared buffer shared by all dynamic-smem kernels
extern __shared__ char dsm_raw[];

// ---------------------------------------------------------------------------
// Decode rw_allow_blocks robustly (bool/int8 vs int32 vs float32).
// ---------------------------------------------------------------------------
__global__ void decode_mask_kernel(const void* p) {
    __shared__ int cnt0, cnt123;
    int tid = threadIdx.x;
    if (tid == 0) { cnt0 = 0; cnt123 = 0; }
    __syncthreads();
    const unsigned char* b = (const unsigned char*)p;
    int l0 = 0, l123 = 0;
    for (int i = tid; i < 1024; i += 256) {
        if (b[i]) { if ((i & 3) == 0) l0++; else l123++; }
    }
    atomicAdd(&cnt0, l0);
    atomicAdd(&cnt123, l123);
    __syncthreads();
    if (cnt123 == 0) {
        const int* a = (const int*)p;
        for (int i = tid; i < 1024; i += 256) g_allow[i] = (a[i] != 0);
    } else if (cnt0 == 0) {
        const float* a = (const float*)p;
        for (int i = tid; i < 1024; i += 256) g_allow[i] = (a[i] != 0.0f);
    } else {
        for (int i = tid; i < 1024; i += 256) g_allow[i] = (b[i] != 0);
    }
}

// ---------------------------------------------------------------------------
// Shared helpers
// ---------------------------------------------------------------------------
#define MMA_BF16(d, a0, a1, a2, a3, b0, b1)                                   \
    asm volatile(                                                             \
        "mma.sync.aligned.m16n8k16.row.col.f32.bf16.bf16.f32 "                \
        "{%0,%1,%2,%3}, {%4,%5,%6,%7}, {%8,%9}, {%0,%1,%2,%3};"               \
        : "+f"(d[0]), "+f"(d[1]), "+f"(d[2]), "+f"(d[3])                      \
        : "r"(a0), "r"(a1), "r"(a2), "r"(a3), "r"(b0), "r"(b1))

#define LDSM_X4(R0, R1, R2, R3, ADDR)                                         \
    asm volatile("ldmatrix.sync.aligned.m8n8.x4.shared.b16 {%0,%1,%2,%3}, [%4];" \
        : "=r"(R0), "=r"(R1), "=r"(R2), "=r"(R3) : "r"(ADDR))

#define LDSM_X2(R0, R1, ADDR)                                                 \
    asm volatile("ldmatrix.sync.aligned.m8n8.x2.shared.b16 {%0,%1}, [%2];"    \
        : "=r"(R0), "=r"(R1) : "r"(ADDR))

__device__ __forceinline__ void cp16(uint32_t saddr, const void* g) {
    asm volatile("cp.async.cg.shared.global [%0], [%1], 16;" :: "r"(saddr), "l"(g));
}
__device__ __forceinline__ void cp_commit() {
    asm volatile("cp.async.commit_group;" ::: "memory");
}

__device__ __forceinline__ void cvt2(float2 f, uint32_t& hi, uint32_t& lo) {
    __nv_bfloat162 h = __floats2bfloat162_rn(f.x, f.y);
    hi = *reinterpret_cast<uint32_t*>(&h);
    __nv_bfloat162 l = __floats2bfloat162_rn(f.x - __bfloat162float(h.x),
                                             f.y - __bfloat162float(h.y));
    lo = *reinterpret_cast<uint32_t*>(&l);
}

__device__ __forceinline__ uint32_t smem_u32(const void* p) {
    return (uint32_t)__cvta_generic_to_shared(p);
}

// fp32 -> bf16 hi/lo, 4 elements per thread
__device__ __forceinline__ void cvt_body(const float* __restrict__ src,
                                         __nv_bfloat16* __restrict__ h,
                                         __nv_bfloat16* __restrict__ l, int i) {
    float4 v = ((const float4*)src)[i];
    uint32_t h0, l0, h1, l1;
    cvt2(make_float2(v.x, v.y), h0, l0);
    cvt2(make_float2(v.z, v.w), h1, l1);
    ((uint2*)h)[i] = make_uint2(h0, h1);
    ((uint2*)l)[i] = make_uint2(l0, l1);
}

__global__ void cvt_hilo(const float* __restrict__ src,
                         __nv_bfloat16* __restrict__ h,
                         __nv_bfloat16* __restrict__ l, int n4) {
    int i = blockIdx.x * blockDim.x + threadIdx.x;
    if (i < n4) cvt_body(src, h, l, i);
}

// fused conversion of three tensors (Wk, Wv, Wo)
__global__ void cvt_hilo3(const float* s0, __nv_bfloat16* h0, __nv_bfloat16* l0, int n0,
                          const float* s1, __nv_bfloat16* h1, __nv_bfloat16* l1, int n1,
                          const float* s2, __nv_bfloat16* h2, __nv_bfloat16* l2, int n2) {
    int i = blockIdx.x * blockDim.x + threadIdx.x;
    if (i < n0) { cvt_body(s0, h0, l0, i); return; }
    i -= n0;
    if (i < n1) { cvt_body(s1, h1, l1, i); return; }
    i -= n1;
    if (i < n2) cvt_body(s2, h2, l2, i);
}

// ---------------------------------------------------------------------------
// GEMM: C = A(:, kB:kB+kLen) * B(:, kB:kB+kLen)^T.
// Block 128x128, BK=32, 2 smem stages, 2 CTAs/SM, ldmatrix frags.
// ---------------------------------------------------------------------------
#define TPADH      40
#define G3_ROW_B   (TPADH * 2)              // 80 bytes
#define G3_TILE_B  (128 * G3_ROW_B)         // 10240
#define G3_STAGE_B (4 * G3_TILE_B)          // 40960
#define G3_SMEM    (2 * G3_STAGE_B)         // 81920

__device__ __forceinline__ void gemm3_core(
    const __nv_bfloat16* __restrict__ Ah, const __nv_bfloat16* __restrict__ Al,
    const __nv_bfloat16* __restrict__ Bh, const __nv_bfloat16* __restrict__ Bl,
    float* __restrict__ C, int K, int ldc, int m0, int n0, int kB, int kLen)
{
    uint32_t sbase = smem_u32(dsm_raw);

    int tid  = threadIdx.x;
    int warp = tid >> 5;
    int lane = tid & 31;
    int wm = warp & 1;
    int wn = warp >> 1;
    int qr = lane >> 2;
    int qc2 = (lane & 3) * 2;

    float acc[4][4][4];
#pragma unroll
    for (int i = 0; i < 4; i++)
#pragma unroll
        for (int j = 0; j < 4; j++)
#pragma unroll
            for (int e = 0; e < 4; e++) acc[i][j][e] = 0.0f;

    const __nv_bfloat16* srcs[4];
    srcs[0] = Ah + (size_t)m0 * K + kB;
    srcs[1] = Al + (size_t)m0 * K + kB;
    srcs[2] = Bh + (size_t)n0 * K + kB;
    srcs[3] = Bl + (size_t)n0 * K + kB;

    int arow = wm * 64 + (lane & 7) + ((lane >> 3) & 1) * 8;
    uint32_t aOff = arow * G3_ROW_B + ((lane >> 4) & 1) * 16;
    int brow = wn * 32 + (lane & 7);
    uint32_t bOff = brow * G3_ROW_B + ((lane >> 3) & 1) * 16;

    const int NITER = kLen / 32;

    {
        uint32_t sb = sbase;
#pragma unroll
        for (int t = 0; t < 8; t++) {
            int id = t * 256 + tid;
            int tile = id >> 9;
            int row  = (id >> 2) & 127;
            int c    = id & 3;
            cp16(sb + tile * G3_TILE_B + row * G3_ROW_B + c * 16,
                 srcs[tile] + (size_t)row * K + c * 8);
        }
        cp_commit();
    }

    for (int it = 0; it < NITER; it++) {
        if (it + 1 < NITER) {
            int k0 = (it + 1) * 32;
            uint32_t sb = sbase + ((it + 1) & 1) * G3_STAGE_B;
#pragma unroll
            for (int t = 0; t < 8; t++) {
                int id = t * 256 + tid;
                int tile = id >> 9;
                int row  = (id >> 2) & 127;
                int c    = id & 3;
                cp16(sb + tile * G3_TILE_B + row * G3_ROW_B + c * 16,
                     srcs[tile] + (size_t)row * K + k0 + c * 8);
            }
            cp_commit();
            asm volatile("cp.async.wait_group 1;" ::: "memory");
        } else {
            asm volatile("cp.async.wait_group 0;" ::: "memory");
        }
        __syncthreads();

        uint32_t sb = sbase + (it & 1) * G3_STAGE_B;
        uint32_t tAh = sb, tAl = sb + G3_TILE_B;
        uint32_t tBh = sb + 2 * G3_TILE_B, tBl = sb + 3 * G3_TILE_B;

#pragma unroll
        for (int k1 = 0; k1 < 2; k1++) {
            uint32_t ko = k1 * 32;
            uint32_t ah[4][4], al[4][4];
#pragma unroll
            for (int mi = 0; mi < 4; mi++) {
                uint32_t off = aOff + mi * (16 * G3_ROW_B) + ko;
                LDSM_X4(ah[mi][0], ah[mi][1], ah[mi][2], ah[mi][3], tAh + off);
                LDSM_X4(al[mi][0], al[mi][1], al[mi][2], al[mi][3], tAl + off);
            }
#pragma unroll
            for (int ni = 0; ni < 4; ni++) {
                uint32_t off = bOff + ni * (8 * G3_ROW_B) + ko;
                uint32_t bh0, bh1, bl0, bl1;
                LDSM_X2(bh0, bh1, tBh + off);
                LDSM_X2(bl0, bl1, tBl + off);
#pragma unroll
                for (int mi = 0; mi < 4; mi++) {
                    MMA_BF16(acc[mi][ni], ah[mi][0], ah[mi][1], ah[mi][2], ah[mi][3], bh0, bh1);
                    MMA_BF16(acc[mi][ni], ah[mi][0], ah[mi][1], ah[mi][2], ah[mi][3], bl0, bl1);
                    MMA_BF16(acc[mi][ni], al[mi][0], al[mi][1], al[mi][2], al[mi][3], bh0, bh1);
                }
            }
        }
        __syncthreads();
    }

#pragma unroll
    for (int mi = 0; mi < 4; mi++) {
#pragma unroll
        for (int ni = 0; ni < 4; ni++) {
            int r = m0 + wm * 64 + mi * 16 + qr;
            int cidx = n0 + wn * 32 + ni * 8 + qc2;
            *(float2*)&C[(size_t)r * ldc + cidx] =
                make_float2(acc[mi][ni][0], acc[mi][ni][1]);
            *(float2*)&C[(size_t)(r + 8) * ldc + cidx] =
                make_float2(acc[mi][ni][2], acc[mi][ni][3]);
        }
    }
}

// qkv with split-K=2: grid (24, 16, 2); z selects K-half and partial buffer.
__global__ __launch_bounds__(256, 2)
void qkv_gemm() {
    int bx = blockIdx.x;
    int m0 = blockIdx.y * 128;
    int ks = blockIdx.z;
    int kB = ks * (EMB / 2);
    if (bx < 16)
        gemm3_core(g_hsh, g_hsl, g_wqh, g_wql, ks ? g_q2 : g_q,
                   EMB, EMB, m0, bx * 128, kB, EMB / 2);
    else if (bx < 20)
        gemm3_core(g_hsh, g_hsl, g_wkh, g_wkl, ks ? g_k2 : g_k,
                   EMB, KVD, m0, (bx - 16) * 128, kB, EMB / 2);
    else
        gemm3_core(g_hsh, g_hsl, g_wvh, g_wvl, ks ? g_v2 : g_v,
                   EMB, KVD, m0, (bx - 20) * 128, kB, EMB / 2);
}

__global__ __launch_bounds__(256, 2)
void out_gemm(float* __restrict__ out) {
    gemm3_core(g_oh, g_ol, g_woh, g_wol, out, EMB, EMB,
               blockIdx.y * 128, blockIdx.x * 128, 0, EMB);
}

// ---------------------------------------------------------------------------
// RoPE: sum split-K partials for q and k, rotate, write in place.
// ---------------------------------------------------------------------------
__global__ void rope_kernel(const float* __restrict__ cosb, const float* __restrict__ sinb) {
    int idx = blockIdx.x * blockDim.x + threadIdx.x;
    const int total = T_SEQ * (NH + NKV) * 32;
    if (idx >= total) return;
    int d = idx & 31;
    int rest = idx >> 5;
    int head = rest % (NH + NKV);
    int t = rest / (NH + NKV);
    float c0 = cosb[t * HD + d];
    float s0 = sinb[t * HD + d];
    float c1 = cosb[t * HD + d + 32];
    float s1 = sinb[t * HD + d + 32];
    float *p1, *p2;
    if (head < NH) {
        size_t off = ((size_t)t * NH + head) * HD;
        p1 = g_q + off; p2 = g_q2 + off;
    } else {
        size_t off = ((size_t)t * NKV + (head - NH)) * HD;
        p1 = g_k + off; p2 = g_k2 + off;
    }
    float x0 = p1[d] + p2[d];
    float x1 = p1[d + 32] + p2[d + 32];
    p1[d]      = x0 * c0 - x1 * s0;
    p1[d + 32] = x1 * c1 + x0 * s1;
}

// ---------------------------------------------------------------------------
// Fused prep: K -> bf16 hi/lo [kv][t][d]; V (partials summed) -> [kv][d][t].
// ---------------------------------------------------------------------------
__global__ void prep_kv_kernel() {
    const int NK = NKV * T_SEQ * HD;
    int o = blockIdx.x * blockDim.x + threadIdx.x;
    if (o < NK) {
        int d  = o & 63;
        int t  = (o >> 6) & (T_SEQ - 1);
        int kv = o >> 17;
        float v = g_k[((size_t)t * NKV + kv) * HD + d];
        __nv_bfloat16 h = __float2bfloat16(v);
        g_kh[o] = h;
        g_kl[o] = __float2bfloat16(v - __bfloat162float(h));
    } else {
        o -= NK;
        if (o >= NK) return;
        int t  = o & (T_SEQ - 1);
        int d  = (o >> 11) & 63;
        int kv = o >> 17;
        size_t goff = ((size_t)t * NKV + kv) * HD + d;
        float v = g_v[goff] + g_v2[goff];
        __nv_bfloat16 h = __float2bfloat16(v);
        g_vh[o] = h;
        g_vl[o] = __float2bfloat16(v - __bfloat162float(h));
    }
}

// ---------------------------------------------------------------------------
// MMA flash attention (best known): 1 head/CTA, double-buffered kb tiles,
// ldmatrix frag loads, exp2 softmax.
// ---------------------------------------------------------------------------
#define TSTR  72
#define TSTRB (TSTR * 2)                 // 144 bytes per tile row
#define ATT_TILE   (64 * TSTR)
#define ATT_TILE_B (ATT_TILE * 2)
#define ATT_STAGE  (4 * ATT_TILE)
#define ATT_STAGE_B (ATT_STAGE * 2)
#define ATT_SMEM   (2 * ATT_STAGE_B)

__device__ __forceinline__ void att_issue_loads(__nv_bfloat16* att_dsm,
                                                int stage, int kb, int kv, int tid) {
    uint32_t base = smem_u32(att_dsm) + stage * ATT_STAGE_B;
#pragma unroll
    for (int t = 0; t < 16; t++) {
        int id   = t * 128 + tid;
        int tile = id >> 9;
        int row  = (id >> 3) & 63;
        int ch   = id & 7;
        const __nv_bfloat16* src;
        if (tile == 0)
            src = g_kh + (((size_t)kv * T_SEQ + kb * 64 + row) * HD + ch * 8);
        else if (tile == 1)
            src = g_kl + (((size_t)kv * T_SEQ + kb * 64 + row) * HD + ch * 8);
        else if (tile == 2)
            src = g_vh + (((size_t)kv * HD + row) * T_SEQ + kb * 64 + ch * 8);
        else
            src = g_vl + (((size_t)kv * HD + row) * T_SEQ + kb * 64 + ch * 8);
        cp16(base + tile * ATT_TILE_B + row * TSTRB + ch * 16, src);
    }
    cp_commit();
}

__global__ __launch_bounds__(128)
void attn_mma_kernel() {
    __nv_bfloat16* att_dsm = (__nv_bfloat16*)dsm_raw;
    int h  = blockIdx.x;
    int qb = blockIdx.y;
    int kv = h >> 2;
    int tid  = threadIdx.x;
    int w    = tid >> 5;
    int lane = tid & 31;
    int qr   = lane >> 2;
    int qc2  = (lane & 3) * 2;
    int rowA = w * 16 + qr;

    const float QSC = 0.125f * 1.4426950408889634f;
    float* sQ = (float*)att_dsm;
    for (int i = tid; i < 64 * 16; i += 128) {
        int row = i >> 4;
        int c4  = (i & 15) * 4;
        float4 v = *(const float4*)&g_q[(((size_t)qb * 64 + row) * NH + h) * HD + c4];
        v.x *= QSC; v.y *= QSC; v.z *= QSC; v.w *= QSC;
        *(float4*)&sQ[row * 68 + c4] = v;
    }
    __syncthreads();

    uint32_t qh[4][4], ql[4][4];
#pragma unroll
    for (int kc = 0; kc < 4; kc++) {
        int k = kc * 16 + qc2;
        cvt2(*(const float2*)&sQ[rowA * 68 + k],           qh[kc][0], ql[kc][0]);
        cvt2(*(const float2*)&sQ[(rowA + 8) * 68 + k],     qh[kc][1], ql[kc][1]);
        cvt2(*(const float2*)&sQ[rowA * 68 + k + 8],       qh[kc][2], ql[kc][2]);
        cvt2(*(const float2*)&sQ[(rowA + 8) * 68 + k + 8], qh[kc][3], ql[kc][3]);
    }
    __syncthreads();

    float m0 = -1e30f, m1 = -1e30f, l0 = 0.0f, l1 = 0.0f;
    float o[8][4];
#pragma unroll
    for (int ni = 0; ni < 8; ni++)
#pragma unroll
        for (int e = 0; e < 4; e++) o[ni][e] = 0.0f;

    uint32_t lanePat = (uint32_t)(lane & 7) * TSTRB + ((lane >> 3) & 1) * 16;
    uint32_t sbase = smem_u32(att_dsm);

    int cur = 0, stage = 0;
    att_issue_loads(att_dsm, 0, 0, kv, tid);

    while (cur < NBLK) {
        int nxt = cur + 1;
        while (nxt < NBLK) {
            if (g_allow[qb * NBLK + nxt] || (nxt < 4) ||
                (nxt <= qb && nxt + 4 >= qb)) break;
            nxt++;
        }
        if (nxt < NBLK) {
            att_issue_loads(att_dsm, stage ^ 1, nxt, kv, tid);
            asm volatile("cp.async.wait_group 1;" ::: "memory");
        } else {
            asm volatile("cp.async.wait_group 0;" ::: "memory");
        }
        __syncthreads();

        int kb = cur;
        int ba = g_allow[qb * NBLK + kb];
        uint32_t sb = sbase + stage * ATT_STAGE_B;
        uint32_t aKh = sb + lanePat;
        uint32_t aKl = aKh + ATT_TILE_B;
        uint32_t aVh = sb + 2 * ATT_TILE_B + lanePat;
        uint32_t aVl = aVh + ATT_TILE_B;

        float s[8][4];
#pragma unroll
        for (int ni = 0; ni < 8; ni++) {
#pragma unroll
            for (int e = 0; e < 4; e++) s[ni][e] = 0.0f;
#pragma unroll
            for (int kc = 0; kc < 4; kc++) {
                uint32_t off = ni * (8 * TSTRB) + kc * 32;
                uint32_t bh0, bh1, bl0, bl1;
                LDSM_X2(bh0, bh1, aKh + off);
                LDSM_X2(bl0, bl1, aKl + off);
                MMA_BF16(s[ni], qh[kc][0], qh[kc][1], qh[kc][2], qh[kc][3], bh0, bh1);
                MMA_BF16(s[ni], qh[kc][0], qh[kc][1], qh[kc][2], qh[kc][3], bl0, bl1);
                MMA_BF16(s[ni], ql[kc][0], ql[kc][1], ql[kc][2], ql[kc][3], bh0, bh1);
            }
        }

        int qi0 = qb * 64 + rowA;
        int qi1 = qi0 + 8;
#pragma unroll
        for (int ni = 0; ni < 8; ni++) {
            int col = kb * 64 + ni * 8 + qc2;
#pragma unroll
            for (int e = 0; e < 4; e++) {
                int kj = col + (e & 1);
                int qi = (e < 2) ? qi0 : qi1;
                bool ok = ba || (kj < WIN) || (kj <= qi && kj + (WIN - 1) >= qi);
                if (!ok) s[ni][e] = -1e30f;
            }
        }

        float mb0 = -1e30f, mb1 = -1e30f;
#pragma unroll
        for (int ni = 0; ni < 8; ni++) {
            mb0 = fmaxf(mb0, fmaxf(s[ni][0], s[ni][1]));
            mb1 = fmaxf(mb1, fmaxf(s[ni][2], s[ni][3]));
        }
        mb0 = fmaxf(mb0, __shfl_xor_sync(0xFFFFFFFF, mb0, 1));
        mb0 = fmaxf(mb0, __shfl_xor_sync(0xFFFFFFFF, mb0, 2));
        mb1 = fmaxf(mb1, __shfl_xor_sync(0xFFFFFFFF, mb1, 1));
        mb1 = fmaxf(mb1, __shfl_xor_sync(0xFFFFFFFF, mb1, 2));

        float mn0 = fmaxf(m0, mb0), mn1 = fmaxf(m1, mb1);
        float sc0 = exp2f(m0 - mn0), sc1 = exp2f(m1 - mn1);
        m0 = mn0; m1 = mn1;
        l0 *= sc0; l1 *= sc1;
#pragma unroll
        for (int ni = 0; ni < 8; ni++) {
            o[ni][0] *= sc0; o[ni][1] *= sc0;
            o[ni][2] *= sc1; o[ni][3] *= sc1;
        }

#pragma unroll
        for (int ni = 0; ni < 8; ni++) {
            s[ni][0] = exp2f(s[ni][0] - m0);
            s[ni][1] = exp2f(s[ni][1] - m0);
            s[ni][2] = exp2f(s[ni][2] - m1);
            s[ni][3] = exp2f(s[ni][3] - m1);
            l0 += s[ni][0] + s[ni][1];
            l1 += s[ni][2] + s[ni][3];
        }

#pragma unroll
        for (int kc = 0; kc < 4; kc++) {
            uint32_t ah[4], al[4];
            cvt2(make_float2(s[2 * kc][0],     s[2 * kc][1]),     ah[0], al[0]);
            cvt2(make_float2(s[2 * kc][2],     s[2 * kc][3]),     ah[1], al[1]);
            cvt2(make_float2(s[2 * kc + 1][0], s[2 * kc + 1][1]), ah[2], al[2]);
            cvt2(make_float2(s[2 * kc + 1][2], s[2 * kc + 1][3]), ah[3], al[3]);
#pragma unroll
            for (int ni = 0; ni < 8; ni++) {
                uint32_t off = ni * (8 * TSTRB) + kc * 32;
                uint32_t bh0, bh1, bl0, bl1;
                LDSM_X2(bh0, bh1, aVh + off);
                LDSM_X2(bl0, bl1, aVl + off);
                MMA_BF16(o[ni], ah[0], ah[1], ah[2], ah[3], bh0, bh1);
                MMA_BF16(o[ni], ah[0], ah[1], ah[2], ah[3], bl0, bl1);
                MMA_BF16(o[ni], al[0], al[1], al[2], al[3], bh0, bh1);
            }
        }
        __syncthreads();
        cur = nxt;
        stage ^= 1;
    }

    l0 += __shfl_xor_sync(0xFFFFFFFF, l0, 1);
    l0 += __shfl_xor_sync(0xFFFFFFFF, l0, 2);
    l1 += __shfl_xor_sync(0xFFFFFFFF, l1, 1);
    l1 += __shfl_xor_sync(0xFFFFFFFF, l1, 2);
    float inv0 = 1.0f / l0, inv1 = 1.0f / l1;

    int qi0 = qb * 64 + rowA;
#pragma unroll
    for (int ni = 0; ni < 8; ni++) {
        int d = ni * 8 + qc2;
        uint32_t hi, lo;
        cvt2(make_float2(o[ni][0] * inv0, o[ni][1] * inv0), hi, lo);
        int idx0 = ((size_t)qi0 * EMB + h * HD + d) >> 1;
        ((uint32_t*)g_oh)[idx0] = hi;
        ((uint32_t*)g_ol)[idx0] = lo;
        cvt2(make_float2(o[ni][2] * inv1, o[ni][3] * inv1), hi, lo);
        int idx1 = ((size_t)(qi0 + 8) * EMB + h * HD + d) >> 1;
        ((uint32_t*)g_oh)[idx1] = hi;
        ((uint32_t*)g_ol)[idx1] = lo;
    }
}

// ---------------------------------------------------------------------------
extern "C" void kernel_launch(void* const* d_in, const int* in_sizes, int n_in,
                              void* d_out, int out_size) {
    const float* hs   = (const float*)d_in[0];
    const float* cosb = (const float*)d_in[1];
    const float* sinb = (const float*)d_in[2];
    const float* Wq   = (const float*)d_in[3];
    const float* Wk   = (const float*)d_in[4];
    const float* Wv   = (const float*)d_in[5];
    const float* Wo   = (const float*)d_in[6];
    const void*  allow = d_in[7];
    float* out = (float*)d_out;

    __nv_bfloat16 *hsh, *hsl, *wqh, *wql, *wkh, *wkl, *wvh, *wvl, *woh, *wol;
    cudaGetSymbolAddress((void**)&hsh, g_hsh);
    cudaGetSymbolAddress((void**)&hsl, g_hsl);
    cudaGetSymbolAddress((void**)&wqh, g_wqh);
    cudaGetSymbolAddress((void**)&wql, g_wql);
    cudaGetSymbolAddress((void**)&wkh, g_wkh);
    cudaGetSymbolAddress((void**)&wkl, g_wkl);
    cudaGetSymbolAddress((void**)&wvh, g_wvh);
    cudaGetSymbolAddress((void**)&wvl, g_wvl);
    cudaGetSymbolAddress((void**)&woh, g_woh);
    cudaGetSymbolAddress((void**)&wol, g_wol);

    cudaFuncSetAttribute(attn_mma_kernel,
                         cudaFuncAttributeMaxDynamicSharedMemorySize, ATT_SMEM);
    cudaFuncSetAttribute(qkv_gemm,
                         cudaFuncAttributeMaxDynamicSharedMemorySize, G3_SMEM);
    cudaFuncSetAttribute(out_gemm,
                         cudaFuncAttributeMaxDynamicSharedMemorySize, G3_SMEM);

    // launch 0-2: conversions (qkv_gemm lands at index 3 = ncu capture slot)
    {
        int n4 = T_SEQ * EMB / 4;
        cvt_hilo<<<(n4 + 255) / 256, 256>>>(hs, hsh, hsl, n4);
        n4 = EMB * EMB / 4;
        cvt_hilo<<<(n4 + 255) / 256, 256>>>(Wq, wqh, wql, n4);
        int nk = KVD * EMB / 4, no = EMB * EMB / 4;
        int tot = 2 * nk + no;
        cvt_hilo3<<<(tot + 255) / 256, 256>>>(Wk, wkh, wkl, nk,
                                              Wv, wvh, wvl, nk,
                                              Wo, woh, wol, no);
    }

    // launch 3: fused QKV projection, split-K=2 (ncu capture target)
    qkv_gemm<<<dim3(24, T_SEQ / 128, 2), 256, G3_SMEM>>>();

    // RoPE (sums split-K partials, rotates in place)
    {
        int total = T_SEQ * (NH + NKV) * 32;
        rope_kernel<<<(total + 255) / 256, 256>>>(cosb, sinb);
    }

    // Pre-convert K (post-RoPE) and V (summed partials) for attention
    prep_kv_kernel<<<(2 * NKV * T_SEQ * HD + 255) / 256, 256>>>();

    // Mask decode
    decode_mask_kernel<<<1, 256>>>(allow);

    // MMA flash attention
    attn_mma_kernel<<<dim3(NH, NBLK), 128, ATT_SMEM>>>();

    // Output projection
    out_gemm<<<dim3(EMB / 128, T_SEQ / 128), 256, G3_SMEM>>>(out);
}